// round 3
// baseline (speedup 1.0000x reference)
#include <cuda_runtime.h>

#define NTH 64
#define REC_STRIDE 260          // floats per thread record (1040B: conflict-free stride)
#define TAB_FLOATS 128
#define NSTEPS 16

__host__ __device__ constexpr int PIDX(int i, int k) {
    return 7 * i - i * (i - 1) / 2 + (k - i - 1);   // upper-tri (i<k) -> 0..27
}

__device__ __forceinline__ float dot8(const float* a, const float* b) {
    float s = a[0] * b[0];
#pragma unroll
    for (int j = 1; j < 8; j++) s = fmaf(a[j], b[j], s);
    return s;
}

__global__ __launch_bounds__(NTH)
void ode_kernel(const float* __restrict__ U0g, const float* __restrict__ epsg,
                const float* __restrict__ W0g, const float* __restrict__ W1g,
                const float* __restrict__ W2g, float* __restrict__ out, int B)
{
    extern __shared__ float sh[];
    float* W2sh = sh;        // 64
    float* AS0  = sh + 64;   // 28 (antisym(W0), upper tri)
    float* AS1  = sh + 96;   // 28 (antisym(W1), upper tri)

    const int tid = threadIdx.x;
    {
        W2sh[tid] = W2g[tid];
        int i = tid >> 3, k = tid & 7;
        if (i < k) {
            AS0[PIDX(i, k)] = 0.5f * (W0g[i * 8 + k] - W0g[k * 8 + i]);
            AS1[PIDX(i, k)] = 0.5f * (W1g[i * 8 + k] - W1g[k * 8 + i]);
        }
    }
    __syncthreads();

    const long b = (long)blockIdx.x * NTH + tid;
    if (b >= B) return;

    float* rec   = sh + TAB_FLOATS + tid * REC_STRIDE;
    float* shU   = rec;        // U_base  [64]
    float* shAcc = rec + 64;   // RK4 acc [64]
    float* shV   = rec + 128;  // eps     [64]
    float* shE   = rec + 192;  // E=v@W2  [64]

    float Us[8][8];

    // ---- init: load U0, eps; zero acc ----
    {
        const float4* u0v = (const float4*)(U0g + (size_t)b * 64);
        const float4* epv = (const float4*)(epsg + (size_t)b * 64);
#pragma unroll
        for (int q = 0; q < 16; q++) {
            float4 u = u0v[q];
            ((float4*)shU)[q] = u;
            int i = q >> 1, j0 = (q & 1) * 4;
            Us[i][j0 + 0] = u.x; Us[i][j0 + 1] = u.y;
            Us[i][j0 + 2] = u.z; Us[i][j0 + 3] = u.w;
            ((float4*)shV)[q] = epv[q];
            ((float4*)shAcc)[q] = make_float4(0.f, 0.f, 0.f, 0.f);
        }
    }
    // ---- E = v @ W2 (once; v is constant over the trajectory) ----
    {
        float Ew[8][8];
#pragma unroll
        for (int i = 0; i < 8; i++)
#pragma unroll
            for (int j = 0; j < 8; j++) Ew[i][j] = 0.f;
#pragma unroll
        for (int m = 0; m < 8; m++) {
            float4 wa = ((const float4*)W2sh)[2 * m], wb = ((const float4*)W2sh)[2 * m + 1];
            float w2r[8] = {wa.x, wa.y, wa.z, wa.w, wb.x, wb.y, wb.z, wb.w};
#pragma unroll
            for (int i = 0; i < 8; i++) {
                float vm = shV[i * 8 + m];
#pragma unroll
                for (int j = 0; j < 8; j++) Ew[i][j] = fmaf(vm, w2r[j], Ew[i][j]);
            }
        }
#pragma unroll
        for (int q = 0; q < 16; q++) {
            int i = q >> 1, j0 = (q & 1) * 4;
            ((float4*)shE)[q] = make_float4(Ew[i][j0], Ew[i][j0 + 1], Ew[i][j0 + 2], Ew[i][j0 + 3]);
        }
    }

    float lj = 0.f;
    const float dt = 1.0f / NSTEPS;   // T_FINAL = 1

#pragma unroll 1
    for (int step = 0; step < NSTEPS; ++step) {
        float t0 = dt * (float)step;
#pragma unroll 1
        for (int s = 0; s < 4; ++s) {
            float ts = t0 + ((s == 0) ? 0.f : ((s == 3) ? dt : 0.5f * dt));

            // ---- P = Us @ W2 ----
            float P[8][8];
#pragma unroll
            for (int k = 0; k < 8; k++) {
                float4 wa = ((const float4*)W2sh)[2 * k], wb = ((const float4*)W2sh)[2 * k + 1];
                float w2r[8] = {wa.x, wa.y, wa.z, wa.w, wb.x, wb.y, wb.z, wb.w};
#pragma unroll
                for (int i = 0; i < 8; i++) {
                    float u = Us[i][k];
                    if (k == 0) {
#pragma unroll
                        for (int j = 0; j < 8; j++) P[i][j] = u * w2r[j];
                    } else {
#pragma unroll
                        for (int j = 0; j < 8; j++) P[i][j] = fmaf(u, w2r[j], P[i][j]);
                    }
                }
            }

            // ---- logj rate:  l = 0.5 * sum_{i<k} D_ik * Xa_ik
            //  D  = asym(E Us^T + P v^T) differences, Xa = asym(v Us^T) differences
            float D[8][8], Xa[8][8];
#pragma unroll
            for (int i = 0; i < 8; i++)
#pragma unroll
                for (int k = i + 1; k < 8; k++) { D[i][k] = 0.f; Xa[i][k] = 0.f; }

#pragma unroll
            for (int r = 0; r < 8; r++) {
                float4 va = ((const float4*)shV)[2 * r], vb = ((const float4*)shV)[2 * r + 1];
                float vr[8] = {va.x, va.y, va.z, va.w, vb.x, vb.y, vb.z, vb.w};
                float4 ea = ((const float4*)shE)[2 * r], eb = ((const float4*)shE)[2 * r + 1];
                float er[8] = {ea.x, ea.y, ea.z, ea.w, eb.x, eb.y, eb.z, eb.w};
#pragma unroll
                for (int k = 0; k < 8; k++) {
                    if (k == r) continue;
                    float x = dot8(vr, Us[k]);   // X[r][k] = v_r . Us_k
                    float y = dot8(er, Us[k]);   // Y[r][k] = E_r . Us_k
                    float z = dot8(P[k], vr);    // Z[k][r] = P_k . v_r
                    if (k > r) {
                        Xa[r][k] += x;
                        D[r][k]  += y;
                        D[r][k]  -= z;
                    } else {
                        Xa[k][r] -= x;
                        D[k][r]  -= y;
                        D[k][r]  += z;
                    }
                }
            }
            float lsum = 0.f;
#pragma unroll
            for (int i = 0; i < 8; i++)
#pragma unroll
                for (int k = i + 1; k < 8; k++) lsum = fmaf(D[i][k], Xa[i][k], lsum);
            float lrate = 0.5f * lsum;

            // ---- A = AS0 + ts*AS1 + asym(P Us^T)  (upper tri only) ----
            float A[8][8];
#pragma unroll
            for (int i = 0; i < 8; i++)
#pragma unroll
                for (int k = i + 1; k < 8; k++) {
                    float d1 = dot8(P[i], Us[k]);
                    float d2 = dot8(P[k], Us[i]);
                    A[i][k] = fmaf(ts, AS1[PIDX(i, k)], AS0[PIDX(i, k)]) + 0.5f * (d1 - d2);
                }

            // ---- kn = A @ Us (A antisymmetric, zero diagonal) ----
            float kn[8][8];
#pragma unroll
            for (int i = 0; i < 8; i++) {
                bool first = true;
#pragma unroll
                for (int k = 0; k < 8; k++) {
                    if (k == i) continue;
                    float a = (k > i) ? A[i][k] : -A[k][i];
                    if (first) {
#pragma unroll
                        for (int j = 0; j < 8; j++) kn[i][j] = a * Us[k][j];
                        first = false;
                    } else {
#pragma unroll
                        for (int j = 0; j < 8; j++) kn[i][j] = fmaf(a, Us[k][j], kn[i][j]);
                    }
                }
            }

            // ---- RK4 stage update ----
            float w = dt * ((s == 1 || s == 2) ? (1.f / 3.f) : (1.f / 6.f));
            lj = fmaf(w, lrate, lj);
            if (s < 3) {
                float am = (s == 2) ? dt : 0.5f * dt;
#pragma unroll
                for (int q = 0; q < 16; q++) {
                    int i = q >> 1, j0 = (q & 1) * 4;
                    float4 ub = ((const float4*)shU)[q];
                    float4 ac = ((float4*)shAcc)[q];
                    ac.x = fmaf(w, kn[i][j0 + 0], ac.x);
                    ac.y = fmaf(w, kn[i][j0 + 1], ac.y);
                    ac.z = fmaf(w, kn[i][j0 + 2], ac.z);
                    ac.w = fmaf(w, kn[i][j0 + 3], ac.w);
                    ((float4*)shAcc)[q] = ac;
                    Us[i][j0 + 0] = fmaf(am, kn[i][j0 + 0], ub.x);
                    Us[i][j0 + 1] = fmaf(am, kn[i][j0 + 1], ub.y);
                    Us[i][j0 + 2] = fmaf(am, kn[i][j0 + 2], ub.z);
                    Us[i][j0 + 3] = fmaf(am, kn[i][j0 + 3], ub.w);
                }
            } else {
#pragma unroll
                for (int q = 0; q < 16; q++) {
                    int i = q >> 1, j0 = (q & 1) * 4;
                    float4 ub = ((const float4*)shU)[q];
                    float4 ac = ((const float4*)shAcc)[q];
                    float n0 = ub.x + fmaf(w, kn[i][j0 + 0], ac.x);
                    float n1 = ub.y + fmaf(w, kn[i][j0 + 1], ac.y);
                    float n2 = ub.z + fmaf(w, kn[i][j0 + 2], ac.z);
                    float n3 = ub.w + fmaf(w, kn[i][j0 + 3], ac.w);
                    Us[i][j0 + 0] = n0; Us[i][j0 + 1] = n1;
                    Us[i][j0 + 2] = n2; Us[i][j0 + 3] = n3;
                    ((float4*)shU)[q]   = make_float4(n0, n1, n2, n3);
                    ((float4*)shAcc)[q] = make_float4(0.f, 0.f, 0.f, 0.f);
                }
            }
        }
    }

    // ---- write outputs: U (B*64 floats) then logj (B floats) ----
    float4* outv = (float4*)(out + (size_t)b * 64);
#pragma unroll
    for (int q = 0; q < 16; q++) {
        int i = q >> 1, j0 = (q & 1) * 4;
        outv[q] = make_float4(Us[i][j0], Us[i][j0 + 1], Us[i][j0 + 2], Us[i][j0 + 3]);
    }
    out[(size_t)B * 64 + b] = lj;
}

extern "C" void kernel_launch(void* const* d_in, const int* in_sizes, int n_in,
                              void* d_out, int out_size)
{
    const float* U0  = (const float*)d_in[0];
    const float* eps = (const float*)d_in[1];
    const float* W0  = (const float*)d_in[2];
    const float* W1  = (const float*)d_in[3];
    const float* W2  = (const float*)d_in[4];

    int B = in_sizes[0] / 64;
    int smem = (TAB_FLOATS + NTH * REC_STRIDE) * (int)sizeof(float);  // 67072 B

    cudaFuncSetAttribute(ode_kernel, cudaFuncAttributeMaxDynamicSharedMemorySize, smem);

    int blocks = (B + NTH - 1) / NTH;
    ode_kernel<<<blocks, NTH, smem>>>(U0, eps, W0, W1, W2, (float*)d_out, B);
}

// round 4
// speedup vs baseline: 1.1969x; 1.1969x over previous
#include <cuda_runtime.h>

#define NTH 64
#define REC_STRIDE 260          // floats per thread record (1040B = 65*16, 260 mod 32 = 4 -> conflict-free)
#define TAB_FLOATS 128
#define NSTEPS 16

typedef unsigned long long u64;

__host__ __device__ constexpr int PIDX(int i, int k) {
    return 7 * i - i * (i - 1) / 2 + (k - i - 1);   // upper-tri (i<k) -> 0..27
}

// ---- packed f32x2 primitives (sm_103a) ----
__device__ __forceinline__ u64 ffma2(u64 a, u64 b, u64 c) {
    u64 d; asm("fma.rn.f32x2 %0, %1, %2, %3;" : "=l"(d) : "l"(a), "l"(b), "l"(c)); return d;
}
__device__ __forceinline__ u64 fmul2(u64 a, u64 b) {
    u64 d; asm("mul.rn.f32x2 %0, %1, %2;" : "=l"(d) : "l"(a), "l"(b)); return d;
}
__device__ __forceinline__ u64 pk2(float x, float y) {
    u64 d; asm("mov.b64 %0, {%1, %2};" : "=l"(d) : "f"(x), "f"(y)); return d;
}
__device__ __forceinline__ float2 up2(u64 a) {
    float2 f; asm("mov.b64 {%0, %1}, %2;" : "=f"(f.x), "=f"(f.y) : "l"(a)); return f;
}
__device__ __forceinline__ u64 bc(float x) { return pk2(x, x); }
__device__ __forceinline__ float hsum(u64 a) { float2 f = up2(a); return f.x + f.y; }

__device__ __forceinline__ float lane(const u64* row, int k) {
    float2 f = up2(row[k >> 1]);
    return (k & 1) ? f.y : f.x;
}

__device__ __forceinline__ float dot8p(const u64* a, const u64* b) {
    u64 s = fmul2(a[0], b[0]);
    s = ffma2(a[1], b[1], s);
    s = ffma2(a[2], b[2], s);
    s = ffma2(a[3], b[3], s);
    return hsum(s);
}

__device__ __forceinline__ void ldrow(u64* dst, const float* src) {
    ulonglong2 t0 = ((const ulonglong2*)src)[0];
    ulonglong2 t1 = ((const ulonglong2*)src)[1];
    dst[0] = t0.x; dst[1] = t0.y; dst[2] = t1.x; dst[3] = t1.y;
}
__device__ __forceinline__ void strow(float* dst, const u64* src) {
    ((ulonglong2*)dst)[0] = make_ulonglong2(src[0], src[1]);
    ((ulonglong2*)dst)[1] = make_ulonglong2(src[2], src[3]);
}

__global__ __launch_bounds__(NTH)
void ode_kernel(const float* __restrict__ U0g, const float* __restrict__ epsg,
                const float* __restrict__ W0g, const float* __restrict__ W1g,
                const float* __restrict__ W2g, float* __restrict__ out, int B)
{
    extern __shared__ float sh[];
    float* W2sh = sh;        // 64
    float* AS0  = sh + 64;   // 28 (antisym(W0), upper tri)
    float* AS1  = sh + 96;   // 28 (antisym(W1), upper tri)

    const int tid = threadIdx.x;
    {
        W2sh[tid] = W2g[tid];
        int i = tid >> 3, k = tid & 7;
        if (i < k) {
            AS0[PIDX(i, k)] = 0.5f * (W0g[i * 8 + k] - W0g[k * 8 + i]);
            AS1[PIDX(i, k)] = 0.5f * (W1g[i * 8 + k] - W1g[k * 8 + i]);
        }
    }
    __syncthreads();

    const long b = (long)blockIdx.x * NTH + tid;
    if (b >= B) return;

    float* rec   = sh + TAB_FLOATS + tid * REC_STRIDE;
    float* shU   = rec;        // U_base  [64]
    float* shAcc = rec + 64;   // RK4 acc [64]
    float* shV   = rec + 128;  // eps     [64]
    float* shE   = rec + 192;  // E=v@W2  [64]

    u64 Us[8][4];

    // ---- init: load U0, eps; store to shared; zero acc; compute E = v@W2 ----
    {
        const float* u0p = U0g + (size_t)b * 64;
        const float* epp = epsg + (size_t)b * 64;
        u64 vv[8][4];
#pragma unroll
        for (int i = 0; i < 8; i++) {
            ldrow(Us[i], u0p + i * 8);
            strow(shU + i * 8, Us[i]);
            ldrow(vv[i], epp + i * 8);
            strow(shV + i * 8, vv[i]);
            u64 z[4] = {0, 0, 0, 0};
            strow(shAcc + i * 8, z);
        }
        u64 Ew[8][4];
#pragma unroll
        for (int m = 0; m < 8; m++) {
            u64 w2m[4];
            ldrow(w2m, W2sh + 8 * m);
#pragma unroll
            for (int i = 0; i < 8; i++) {
                u64 a = bc(lane(vv[i], m));
                if (m == 0) {
#pragma unroll
                    for (int q = 0; q < 4; q++) Ew[i][q] = fmul2(a, w2m[q]);
                } else {
#pragma unroll
                    for (int q = 0; q < 4; q++) Ew[i][q] = ffma2(a, w2m[q], Ew[i][q]);
                }
            }
        }
#pragma unroll
        for (int i = 0; i < 8; i++) strow(shE + i * 8, Ew[i]);
    }

    float lj = 0.f;
    const float dt = 1.0f / NSTEPS;   // T_FINAL = 1

#pragma unroll 1
    for (int step = 0; step < NSTEPS; ++step) {
        float t0 = dt * (float)step;
#pragma unroll 1
        for (int s = 0; s < 4; ++s) {
            float ts = t0 + ((s == 0) ? 0.f : ((s == 3) ? dt : 0.5f * dt));

            // ---- P = Us @ W2 ----
            u64 P[8][4];
#pragma unroll
            for (int k = 0; k < 8; k++) {
                u64 w2k[4];
                ldrow(w2k, W2sh + 8 * k);
#pragma unroll
                for (int i = 0; i < 8; i++) {
                    u64 a = bc(lane(Us[i], k));
                    if (k == 0) {
#pragma unroll
                        for (int q = 0; q < 4; q++) P[i][q] = fmul2(a, w2k[q]);
                    } else {
#pragma unroll
                        for (int q = 0; q < 4; q++) P[i][q] = ffma2(a, w2k[q], P[i][q]);
                    }
                }
            }

            // ---- Xa = asym2(v Us^T), 28 upper-tri scalars, row-order (8 v-row loads) ----
            float Xa[28];
#pragma unroll
            for (int r = 0; r < 8; r++) {
                u64 vr[4];
                ldrow(vr, shV + 8 * r);
#pragma unroll
                for (int k = 0; k < 8; k++) {
                    if (k == r) continue;
                    float d = dot8p(vr, Us[k]);
                    if (k > r) Xa[PIDX(r, k)] = d;      // first touch (r < k)
                    else       Xa[PIDX(k, r)] -= d;     // second touch (r > k)
                }
            }

            // ---- A = AS0 + ts*AS1 + asym(P Us^T) (upper tri), all-register dots ----
            float A[28];
#pragma unroll
            for (int i = 0; i < 8; i++)
#pragma unroll
                for (int k = i + 1; k < 8; k++) {
                    float d1 = dot8p(P[i], Us[k]);
                    float d2 = dot8p(P[k], Us[i]);
                    A[PIDX(i, k)] = fmaf(ts, AS1[PIDX(i, k)], AS0[PIDX(i, k)]) + 0.5f * (d1 - d2);
                }

            // ---- lrate = 0.5 * ( <E, Xa@Us> + <v, Xa^T@P> ) ----
            float lY = 0.f;
#pragma unroll
            for (int i = 0; i < 8; i++) {
                u64 Bi[4];
                bool first = true;
#pragma unroll
                for (int k = 0; k < 8; k++) {
                    if (k == i) continue;
                    float sc = (k > i) ? Xa[PIDX(i, k)] : -Xa[PIDX(k, i)];
                    u64 sb = bc(sc);
                    if (first) {
#pragma unroll
                        for (int q = 0; q < 4; q++) Bi[q] = fmul2(sb, Us[k][q]);
                        first = false;
                    } else {
#pragma unroll
                        for (int q = 0; q < 4; q++) Bi[q] = ffma2(sb, Us[k][q], Bi[q]);
                    }
                }
                u64 Ei[4];
                ldrow(Ei, shE + 8 * i);
                lY += dot8p(Ei, Bi);
            }
            float lZ = 0.f;
#pragma unroll
            for (int k = 0; k < 8; k++) {
                u64 Ck[4];
                bool first = true;
#pragma unroll
                for (int i = 0; i < 8; i++) {
                    if (i == k) continue;
                    float sc = (i < k) ? Xa[PIDX(i, k)] : -Xa[PIDX(k, i)];  // Xa_ik signed
                    u64 sb = bc(sc);
                    if (first) {
#pragma unroll
                        for (int q = 0; q < 4; q++) Ck[q] = fmul2(sb, P[i][q]);
                        first = false;
                    } else {
#pragma unroll
                        for (int q = 0; q < 4; q++) Ck[q] = ffma2(sb, P[i][q], Ck[q]);
                    }
                }
                u64 vk[4];
                ldrow(vk, shV + 8 * k);
                lZ += dot8p(vk, Ck);
            }
            float lrate = 0.5f * (lY + lZ);

            // ---- kn = A @ Us (A antisymmetric, zero diagonal) ----
            u64 kn[8][4];
#pragma unroll
            for (int i = 0; i < 8; i++) {
                bool first = true;
#pragma unroll
                for (int k = 0; k < 8; k++) {
                    if (k == i) continue;
                    float a = (k > i) ? A[PIDX(i, k)] : -A[PIDX(k, i)];
                    u64 ab = bc(a);
                    if (first) {
#pragma unroll
                        for (int q = 0; q < 4; q++) kn[i][q] = fmul2(ab, Us[k][q]);
                        first = false;
                    } else {
#pragma unroll
                        for (int q = 0; q < 4; q++) kn[i][q] = ffma2(ab, Us[k][q], kn[i][q]);
                    }
                }
            }

            // ---- RK4 stage update ----
            float w = dt * ((s == 1 || s == 2) ? (1.f / 3.f) : (1.f / 6.f));
            lj = fmaf(w, lrate, lj);
            u64 wb = bc(w);
            if (s < 3) {
                float am = (s == 2) ? dt : 0.5f * dt;
                u64 ab = bc(am);
#pragma unroll
                for (int i = 0; i < 8; i++) {
                    u64 ub[4], ac[4];
                    ldrow(ub, shU + 8 * i);
                    ldrow(ac, shAcc + 8 * i);
#pragma unroll
                    for (int q = 0; q < 4; q++) {
                        ac[q] = ffma2(wb, kn[i][q], ac[q]);
                        Us[i][q] = ffma2(ab, kn[i][q], ub[q]);
                    }
                    strow(shAcc + 8 * i, ac);
                }
            } else {
                const u64 zero2 = 0;
#pragma unroll
                for (int i = 0; i < 8; i++) {
                    u64 ub[4], ac[4], z[4];
                    ldrow(ub, shU + 8 * i);
                    ldrow(ac, shAcc + 8 * i);
#pragma unroll
                    for (int q = 0; q < 4; q++) {
                        u64 t = ffma2(wb, kn[i][q], ac[q]);
                        u64 nv;
                        asm("add.rn.f32x2 %0, %1, %2;" : "=l"(nv) : "l"(ub[q]), "l"(t));
                        Us[i][q] = nv;
                        z[q] = zero2;
                    }
                    strow(shU + 8 * i, Us[i]);
                    strow(shAcc + 8 * i, z);
                }
            }
        }
    }

    // ---- write outputs: U (B*64 floats) then logj (B floats) ----
    float* orow = out + (size_t)b * 64;
#pragma unroll
    for (int i = 0; i < 8; i++) strow(orow + i * 8, Us[i]);
    out[(size_t)B * 64 + b] = lj;
}

extern "C" void kernel_launch(void* const* d_in, const int* in_sizes, int n_in,
                              void* d_out, int out_size)
{
    const float* U0  = (const float*)d_in[0];
    const float* eps = (const float*)d_in[1];
    const float* W0  = (const float*)d_in[2];
    const float* W1  = (const float*)d_in[3];
    const float* W2  = (const float*)d_in[4];

    int B = in_sizes[0] / 64;
    int smem = (TAB_FLOATS + NTH * REC_STRIDE) * (int)sizeof(float);  // 67072 B

    cudaFuncSetAttribute(ode_kernel, cudaFuncAttributeMaxDynamicSharedMemorySize, smem);

    int blocks = (B + NTH - 1) / NTH;
    ode_kernel<<<blocks, NTH, smem>>>(U0, eps, W0, W1, W2, (float*)d_out, B);
}

// round 5
// speedup vs baseline: 1.6452x; 1.3745x over previous
#include <cuda_runtime.h>

#define NTH 256
#define MPB 32            // matrices per block (8 lanes each)
#define ROW 12            // floats per row in shared (48B, conflict-free permutation)
#define ARR 96            // floats per 8-row array
#define MREC 384          // floats per matrix record: Us | P | V | E
#define HDR 192           // W2(64) + AS0f(64) + AS1f(64)
#define NSTEPS 16

typedef unsigned long long u64;

// ---- packed f32x2 primitives (sm_103a) ----
__device__ __forceinline__ u64 ffma2(u64 a, u64 b, u64 c) {
    u64 d; asm("fma.rn.f32x2 %0, %1, %2, %3;" : "=l"(d) : "l"(a), "l"(b), "l"(c)); return d;
}
__device__ __forceinline__ u64 fmul2(u64 a, u64 b) {
    u64 d; asm("mul.rn.f32x2 %0, %1, %2;" : "=l"(d) : "l"(a), "l"(b)); return d;
}
__device__ __forceinline__ u64 fadd2(u64 a, u64 b) {
    u64 d; asm("add.rn.f32x2 %0, %1, %2;" : "=l"(d) : "l"(a), "l"(b)); return d;
}
__device__ __forceinline__ u64 pk2(float x, float y) {
    u64 d; asm("mov.b64 %0, {%1, %2};" : "=l"(d) : "f"(x), "f"(y)); return d;
}
__device__ __forceinline__ float2 up2(u64 a) {
    float2 f; asm("mov.b64 {%0, %1}, %2;" : "=f"(f.x), "=f"(f.y) : "l"(a)); return f;
}
__device__ __forceinline__ u64 bc(float x) { return pk2(x, x); }

__device__ __forceinline__ float lanef(const u64* row, int k) {
    float2 f = up2(row[k >> 1]);
    return (k & 1) ? f.y : f.x;
}
__device__ __forceinline__ float dot8p(const u64* a, const u64* b) {
    u64 s = fmul2(a[0], b[0]);
    s = ffma2(a[1], b[1], s);
    s = ffma2(a[2], b[2], s);
    s = ffma2(a[3], b[3], s);
    float2 f = up2(s);
    return f.x + f.y;
}
// shared row <-> u64[4]  (rows are 16B-aligned: base 768B + m*1536B + j*48B)
__device__ __forceinline__ void ldr(u64* d, const float* s) {
    ulonglong2 t0 = *(const ulonglong2*)s;
    ulonglong2 t1 = *(const ulonglong2*)(s + 4);
    d[0] = t0.x; d[1] = t0.y; d[2] = t1.x; d[3] = t1.y;
}
__device__ __forceinline__ void str(float* d, const u64* s) {
    *(ulonglong2*)d       = make_ulonglong2(s[0], s[1]);
    *(ulonglong2*)(d + 4) = make_ulonglong2(s[2], s[3]);
}

__global__ __launch_bounds__(NTH, 2)
void ode_kernel(const float* __restrict__ U0g, const float* __restrict__ epsg,
                const float* __restrict__ W0g, const float* __restrict__ W1g,
                const float* __restrict__ W2g, float* __restrict__ out, int B)
{
    extern __shared__ float sh[];
    float* W2sh = sh;         // 64: W2 row-major
    float* AS0f = sh + 64;    // 64: full antisym(W0)
    float* AS1f = sh + 128;   // 64: full antisym(W1)

    const int tid = threadIdx.x;
    if (tid < 64) {
        W2sh[tid] = W2g[tid];
        int ii = tid >> 3, kk = tid & 7;
        AS0f[tid] = 0.5f * (W0g[ii * 8 + kk] - W0g[kk * 8 + ii]);
        AS1f[tid] = 0.5f * (W1g[ii * 8 + kk] - W1g[kk * 8 + ii]);
    }
    __syncthreads();

    const int i = tid & 7;                        // my row
    const long bm = (long)blockIdx.x * MPB + (tid >> 3);   // my matrix
    const long bml = (bm < B) ? bm : (long)(B - 1);        // clamp for loads

    float* rec = sh + HDR + (size_t)(tid >> 3) * MREC;
    float* rU = rec;                // Us rows, stride ROW
    float* rP = rec + ARR;
    float* rV = rec + 2 * ARR;
    float* rE = rec + 3 * ARR;
    float* myU = rU + i * ROW;
    float* myP = rP + i * ROW;

    // ---- init: load my rows of U0 and eps; E row = v @ W2 ----
    u64 u[4], v[4], ub[4], ac[4];
    ldr(u, U0g + bml * 64 + i * 8);
    ldr(v, epsg + bml * 64 + i * 8);
#pragma unroll
    for (int q = 0; q < 4; q++) { ub[q] = u[q]; ac[q] = 0ull; }
    {
        u64 ew[4];
#pragma unroll
        for (int mm = 0; mm < 8; mm++) {
            u64 w2r[4];
            ldr(w2r, W2sh + 8 * mm);
            u64 a = bc(lanef(v, mm));
            if (mm == 0) {
#pragma unroll
                for (int q = 0; q < 4; q++) ew[q] = fmul2(a, w2r[q]);
            } else {
#pragma unroll
                for (int q = 0; q < 4; q++) ew[q] = ffma2(a, w2r[q], ew[q]);
            }
        }
        str(rV + i * ROW, v);
        str(rE + i * ROW, ew);
    }
    __syncwarp();

    float lj = 0.f;
    const float dt = 1.0f / NSTEPS;   // T_FINAL = 1

#pragma unroll 1
    for (int st = 0; st < NSTEPS * 4; ++st) {
        const int step = st >> 2, s = st & 3;
        const float t0 = dt * (float)step;
        const float ts = t0 + ((s == 0) ? 0.f : ((s == 3) ? dt : 0.5f * dt));

        // publish my current Us row (syncwarp: WAR vs prior stage's reads)
        __syncwarp();
        str(myU, u);

        // ---- my P row: p = sum_m u[m] * W2row_m  (W2 broadcast loads) ----
        u64 p[4];
#pragma unroll
        for (int mm = 0; mm < 8; mm++) {
            u64 w2r[4];
            ldr(w2r, W2sh + 8 * mm);
            u64 a = bc(lanef(u, mm));
            if (mm == 0) {
#pragma unroll
                for (int q = 0; q < 4; q++) p[q] = fmul2(a, w2r[q]);
            } else {
#pragma unroll
                for (int q = 0; q < 4; q++) p[q] = ffma2(a, w2r[q], p[q]);
            }
        }
        str(myP, p);
        __syncwarp();

        // ---- rotation rounds: pairwise terms with row j = (i+r)&7 ----
        u64 kn[4] = {0, 0, 0, 0};   // row i of A @ Us
        u64 Bv[4] = {0, 0, 0, 0};   // row i of Xa @ Us
        u64 Cv[4] = {0, 0, 0, 0};   // col i of Xa^T applied to P:  C_i = sum_j Xa[j][i] P_j
#pragma unroll
        for (int r = 1; r < 8; ++r) {
            const int j = (i + r) & 7;
            u64 Uj[4], Pj[4], Vj[4];
            ldr(Uj, rU + j * ROW);
            ldr(Pj, rP + j * ROW);
            ldr(Vj, rV + j * ROW);
            float dPU = dot8p(p, Uj);     // (P Us^T)[i][j]
            float dUP = dot8p(Pj, u);     // (P Us^T)[j][i]
            float a   = fmaf(ts, AS1f[i * 8 + j], AS0f[i * 8 + j]) + 0.5f * (dPU - dUP);
            float xij = dot8p(v, Uj);     // (v Us^T)[i][j]
            float xji = dot8p(Vj, u);     // (v Us^T)[j][i]
            float xa  = xij - xji;        // Xa[i][j] (antisym, both orientations)
            u64 ab  = bc(a);
            u64 xb  = bc(xa);
            u64 nxb = bc(-xa);            // Xa[j][i]
#pragma unroll
            for (int q = 0; q < 4; q++) {
                kn[q] = ffma2(ab,  Uj[q], kn[q]);
                Bv[q] = ffma2(xb,  Uj[q], Bv[q]);
                Cv[q] = ffma2(nxb, Pj[q], Cv[q]);
            }
        }

        // ---- logj rate partial for this row ----
        u64 ev[4];
        ldr(ev, rE + i * ROW);
        float lY = dot8p(ev, Bv);
        float lZ = dot8p(v, Cv);
        const float w = dt * ((s == 1 || s == 2) ? (1.f / 3.f) : (1.f / 6.f));
        lj = fmaf(0.5f * w, lY + lZ, lj);

        // ---- RK4 stage update of my row ----
        u64 wb = bc(w);
        if (s < 3) {
            float am = (s == 2) ? dt : 0.5f * dt;
            u64 ab2 = bc(am);
#pragma unroll
            for (int q = 0; q < 4; q++) {
                ac[q] = ffma2(wb, kn[q], ac[q]);
                u[q]  = ffma2(ab2, kn[q], ub[q]);
            }
        } else {
#pragma unroll
            for (int q = 0; q < 4; q++) {
                u64 t = ffma2(wb, kn[q], ac[q]);
                u[q]  = fadd2(ub[q], t);
                ub[q] = u[q];
                ac[q] = 0ull;
            }
        }
    }

    // ---- outputs ----
    if (bm < B) {
        str(out + bm * 64 + i * 8, u);
        float sred = lj;
        sred += __shfl_xor_sync(0xffffffffu, sred, 1);
        sred += __shfl_xor_sync(0xffffffffu, sred, 2);
        sred += __shfl_xor_sync(0xffffffffu, sred, 4);
        if (i == 0) out[(size_t)B * 64 + bm] = sred;
    }
}

extern "C" void kernel_launch(void* const* d_in, const int* in_sizes, int n_in,
                              void* d_out, int out_size)
{
    const float* U0  = (const float*)d_in[0];
    const float* eps = (const float*)d_in[1];
    const float* W0  = (const float*)d_in[2];
    const float* W1  = (const float*)d_in[3];
    const float* W2  = (const float*)d_in[4];

    int B = in_sizes[0] / 64;
    int smem = (HDR + MPB * MREC) * (int)sizeof(float);   // 49920 B

    cudaFuncSetAttribute(ode_kernel, cudaFuncAttributeMaxDynamicSharedMemorySize, smem);

    int blocks = (B + MPB - 1) / MPB;
    ode_kernel<<<blocks, NTH, smem>>>(U0, eps, W0, W1, W2, (float*)d_out, B);
}

// round 6
// speedup vs baseline: 2.0843x; 1.2669x over previous
#include <cuda_runtime.h>

#define NTH 256
#define MPB 32            // matrices per block (8 lanes each)
#define ROW 12            // floats per Us row in shared (48B)
#define MREC 104          // floats per matrix record (416B, 16B-aligned rows)
#define HDR 256           // W2(64) + negW2T(64) + ASpair(128)
#define NSTEPS 16

typedef unsigned long long u64;

// ---- packed f32x2 primitives (sm_103a) ----
__device__ __forceinline__ u64 ffma2(u64 a, u64 b, u64 c) {
    u64 d; asm("fma.rn.f32x2 %0, %1, %2, %3;" : "=l"(d) : "l"(a), "l"(b), "l"(c)); return d;
}
__device__ __forceinline__ u64 fmul2(u64 a, u64 b) {
    u64 d; asm("mul.rn.f32x2 %0, %1, %2;" : "=l"(d) : "l"(a), "l"(b)); return d;
}
__device__ __forceinline__ u64 fadd2(u64 a, u64 b) {
    u64 d; asm("add.rn.f32x2 %0, %1, %2;" : "=l"(d) : "l"(a), "l"(b)); return d;
}
__device__ __forceinline__ u64 pk2(float x, float y) {
    u64 d; asm("mov.b64 %0, {%1, %2};" : "=l"(d) : "f"(x), "f"(y)); return d;
}
__device__ __forceinline__ float2 up2(u64 a) {
    float2 f; asm("mov.b64 {%0, %1}, %2;" : "=f"(f.x), "=f"(f.y) : "l"(a)); return f;
}
__device__ __forceinline__ u64 bc(float x) { return pk2(x, x); }

__device__ __forceinline__ float lanef(const u64* row, int k) {
    float2 f = up2(row[k >> 1]);
    return (k & 1) ? f.y : f.x;
}
__device__ __forceinline__ float dot8p(const u64* a, const u64* b) {
    u64 s = fmul2(a[0], b[0]);
    s = ffma2(a[1], b[1], s);
    s = ffma2(a[2], b[2], s);
    s = ffma2(a[3], b[3], s);
    float2 f = up2(s);
    return f.x + f.y;
}
__device__ __forceinline__ void ldr(u64* d, const float* s) {
    ulonglong2 t0 = *(const ulonglong2*)s;
    ulonglong2 t1 = *(const ulonglong2*)(s + 4);
    d[0] = t0.x; d[1] = t0.y; d[2] = t1.x; d[3] = t1.y;
}
__device__ __forceinline__ void str(float* d, const u64* s) {
    *(ulonglong2*)d       = make_ulonglong2(s[0], s[1]);
    *(ulonglong2*)(d + 4) = make_ulonglong2(s[2], s[3]);
}

__global__ __launch_bounds__(NTH, 2)
void ode_kernel(const float* __restrict__ U0g, const float* __restrict__ epsg,
                const float* __restrict__ W0g, const float* __restrict__ W1g,
                const float* __restrict__ W2g, float* __restrict__ out, int B)
{
    extern __shared__ float sh[];
    float* W2sh  = sh;         // 64: W2 row-major
    float* W2Tn  = sh + 64;    // 64: W2Tn[n*8+m] = -W2[m][n]
    float* ASP   = sh + 128;   // 128: ASP[2*(i*8+k)] = antisym(W0)[i][k], [+1] = antisym(W1)[i][k]

    const int tid = threadIdx.x;
    if (tid < 64) {
        int ii = tid >> 3, kk = tid & 7;
        float w2 = W2g[tid];
        W2sh[tid] = w2;
        W2Tn[kk * 8 + ii] = -w2;
        ASP[2 * tid]     = 0.5f * (W0g[ii * 8 + kk] - W0g[kk * 8 + ii]);
        ASP[2 * tid + 1] = 0.5f * (W1g[ii * 8 + kk] - W1g[kk * 8 + ii]);
    }
    __syncthreads();

    const int i = tid & 7;                                  // my row
    const long bm = (long)blockIdx.x * MPB + (tid >> 3);    // my matrix
    const long bml = (bm < B) ? bm : (long)(B - 1);

    float* rU  = sh + HDR + (size_t)(tid >> 3) * MREC;      // Us rows, stride ROW
    float* myU = rU + i * ROW;

    // ---- lane-own state ----
    u64 u[4], ub[4], ac[4], v[4], e[4], g[4];
    ldr(u, U0g + bml * 64 + i * 8);
    ldr(v, epsg + bml * 64 + i * 8);
#pragma unroll
    for (int q = 0; q < 4; q++) { ub[q] = u[q]; ac[q] = 0ull; }

    // e = v @ W2 (row i of eps times W2);  g[m] = (W2 @ v)[m] = sum_n W2[m][n] v[n]
    {
        u64 gn[4];
#pragma unroll
        for (int m = 0; m < 8; m++) {
            u64 w2r[4], wtn[4];
            ldr(w2r, W2sh + 8 * m);
            ldr(wtn, W2Tn + 8 * m);
            u64 a = bc(lanef(v, m));
            if (m == 0) {
#pragma unroll
                for (int q = 0; q < 4; q++) { e[q] = fmul2(a, w2r[q]); gn[q] = fmul2(a, wtn[q]); }
            } else {
#pragma unroll
                for (int q = 0; q < 4; q++) { e[q] = ffma2(a, w2r[q], e[q]); gn[q] = ffma2(a, wtn[q], gn[q]); }
            }
        }
        u64 m1 = bc(-1.f);
#pragma unroll
        for (int q = 0; q < 4; q++) g[q] = fmul2(m1, gn[q]);   // un-negate
    }

    float lj = 0.f;
    const float dt = 1.0f / NSTEPS;   // T_FINAL = 1

#pragma unroll 1
    for (int st = 0; st < NSTEPS * 4; ++st) {
        const int step = st >> 2, s = st & 3;
        const float t0 = dt * (float)step;
        const float ts = t0 + ((s == 0) ? 0.f : ((s == 3) ? dt : 0.5f * dt));

        __syncwarp();          // WAR vs previous stage's reads of rU
        str(myU, u);

        // ---- p = u @ W2, qn = -(W2 @ u);  pm = p - q = p + qn ----
        u64 pm[4];
        {
            u64 p[4], qn[4];
#pragma unroll
            for (int m = 0; m < 8; m++) {
                u64 w2r[4], wtn[4];
                ldr(w2r, W2sh + 8 * m);
                ldr(wtn, W2Tn + 8 * m);
                u64 a = bc(lanef(u, m));
                if (m == 0) {
#pragma unroll
                    for (int q = 0; q < 4; q++) { p[q] = fmul2(a, w2r[q]); qn[q] = fmul2(a, wtn[q]); }
                } else {
#pragma unroll
                    for (int q = 0; q < 4; q++) { p[q] = ffma2(a, w2r[q], p[q]); qn[q] = ffma2(a, wtn[q], qn[q]); }
                }
            }
#pragma unroll
            for (int q = 0; q < 4; q++) pm[q] = fadd2(p[q], qn[q]);
        }
        __syncwarp();          // rU rows published by all lanes

        // ---- pass 1: rounds, only U_j loaded; all dots lane-local ----
        float xij[8], yv[8], zf[8];
        u64 kn[4] = {0, 0, 0, 0};
#pragma unroll
        for (int r = 1; r < 8; ++r) {
            const int j = (i + r) & 7;
            u64 Uj[4];
            ldr(Uj, rU + j * ROW);
            float2 as = *(const float2*)(ASP + 2 * (i * 8 + j));
            float dA = dot8p(pm, Uj);                    // (P Us^T)[i][j] - (P Us^T)[j][i]
            float a  = fmaf(ts, as.y, as.x) + 0.5f * dA; // A[i][j]
            xij[r] = dot8p(v, Uj);                       // (v Us^T)[i][j]
            yv[r]  = dot8p(e, Uj);                       // Y[i][j] = E_i . U_j
            zf[r]  = dot8p(g, Uj);                       // Z[(i+r), i] = U_j . g_i
            u64 ab = bc(a);
#pragma unroll
            for (int q = 0; q < 4; q++) kn[q] = ffma2(ab, Uj[q], kn[q]);
        }

        // ---- pass 2: scalar shuffles close the antisymmetric pairs ----
        float lsum = 0.f;
#pragma unroll
        for (int r = 1; r < 8; ++r) {
            const int j = (i + r) & 7;
            float xji = __shfl_sync(0xffffffffu, xij[8 - r], j, 8);  // (v Us^T)[j][i]
            float zij = __shfl_sync(0xffffffffu, zf[8 - r],  j, 8);  // Z[i][j] = u_i . g_j
            float xa  = xij[r] - xji;                                 // Xa[i][j]
            lsum = fmaf(xa, yv[r] + zij, lsum);
        }

        // ---- RK4 stage update ----
        const float w = dt * ((s == 1 || s == 2) ? (1.f / 3.f) : (1.f / 6.f));
        lj = fmaf(0.5f * w, lsum, lj);
        u64 wb = bc(w);
        if (s < 3) {
            float am = (s == 2) ? dt : 0.5f * dt;
            u64 ab2 = bc(am);
#pragma unroll
            for (int q = 0; q < 4; q++) {
                ac[q] = ffma2(wb, kn[q], ac[q]);
                u[q]  = ffma2(ab2, kn[q], ub[q]);
            }
        } else {
#pragma unroll
            for (int q = 0; q < 4; q++) {
                u64 t = ffma2(wb, kn[q], ac[q]);
                u[q]  = fadd2(ub[q], t);
                ub[q] = u[q];
                ac[q] = 0ull;
            }
        }
    }

    // ---- outputs ----
    if (bm < B) {
        str(out + bm * 64 + i * 8, u);
        float sred = lj;
        sred += __shfl_xor_sync(0xffffffffu, sred, 1);
        sred += __shfl_xor_sync(0xffffffffu, sred, 2);
        sred += __shfl_xor_sync(0xffffffffu, sred, 4);
        if (i == 0) out[(size_t)B * 64 + bm] = sred;
    }
}

extern "C" void kernel_launch(void* const* d_in, const int* in_sizes, int n_in,
                              void* d_out, int out_size)
{
    const float* U0  = (const float*)d_in[0];
    const float* eps = (const float*)d_in[1];
    const float* W0  = (const float*)d_in[2];
    const float* W1  = (const float*)d_in[3];
    const float* W2  = (const float*)d_in[4];

    int B = in_sizes[0] / 64;
    int smem = (HDR + MPB * MREC) * (int)sizeof(float);   // 14336 B

    cudaFuncSetAttribute(ode_kernel, cudaFuncAttributeMaxDynamicSharedMemorySize, smem);

    int blocks = (B + MPB - 1) / MPB;
    ode_kernel<<<blocks, NTH, smem>>>(U0, eps, W0, W1, W2, (float*)d_out, B);
}